// round 1
// baseline (speedup 1.0000x reference)
#include <cuda_runtime.h>
#include <cstdint>

// ---------------------------------------------------------------------------
// BitNetLinear: out = (x @ qw^T) * w_scale + bias * input_scale
//   qw = ternary(weight, scale = mean|weight|), input_scale = mean|x|
// Shapes: x [2,2048,4096] fp32, weight [4096,4096] fp32, bias [4096] fp32
// GEMM: M=4096, N=4096, K=4096 (137.4 GFLOP) via tf32 mma.sync m16n8k8
// ---------------------------------------------------------------------------

#define M_TOT 4096
#define N_TOT 4096
#define K_TOT 4096
#define NELEM 16777216  // 4096*4096 == 2*2048*4096

// Scratch (allocation-free rule: __device__ globals)
__device__ __align__(128) float  g_qw[(size_t)N_TOT * K_TOT];  // ternary weight as fp32
__device__ double g_part[2048];   // [0:1024) = x partials, [1024:2048) = w partials
__device__ float  g_scales[2];    // [0] = input_scale, [1] = w_scale

// ---------------------------------------------------------------------------
// Pass 1: per-block abs-sum partials (double accumulation for scale accuracy)
// ---------------------------------------------------------------------------
__global__ void k_reduce_abs(const float* __restrict__ src, int n4, int partOff) {
    double s = 0.0;
    const float4* p = (const float4*)src;
    for (int i = blockIdx.x * blockDim.x + threadIdx.x; i < n4;
         i += gridDim.x * blockDim.x) {
        float4 v = p[i];
        s += (double)(fabsf(v.x) + fabsf(v.y)) + (double)(fabsf(v.z) + fabsf(v.w));
    }
    __shared__ double sm[256];
    sm[threadIdx.x] = s;
    __syncthreads();
    for (int o = 128; o > 0; o >>= 1) {
        if (threadIdx.x < o) sm[threadIdx.x] += sm[threadIdx.x + o];
        __syncthreads();
    }
    if (threadIdx.x == 0) g_part[partOff + blockIdx.x] = sm[0];
}

// ---------------------------------------------------------------------------
// Pass 2: finalize both scales
// ---------------------------------------------------------------------------
__global__ void k_finalize() {
    const int tid = threadIdx.x;
    __shared__ double sm[256];
    double sx = 0.0, sw = 0.0;
    for (int i = tid; i < 1024; i += 256) {
        sx += g_part[i];
        sw += g_part[1024 + i];
    }
    sm[tid] = sx;
    __syncthreads();
    for (int o = 128; o > 0; o >>= 1) {
        if (tid < o) sm[tid] += sm[tid + o];
        __syncthreads();
    }
    double totx = sm[0];
    __syncthreads();
    sm[tid] = sw;
    __syncthreads();
    for (int o = 128; o > 0; o >>= 1) {
        if (tid < o) sm[tid] += sm[tid + o];
        __syncthreads();
    }
    if (tid == 0) {
        g_scales[0] = fmaxf((float)(totx / (double)NELEM), 1e-8f);
        g_scales[1] = fmaxf((float)(sm[0] / (double)NELEM), 1e-8f);
    }
}

// ---------------------------------------------------------------------------
// Pass 3: ternary quantize weight -> g_qw (match reference: |w/s| > 0.5)
// ---------------------------------------------------------------------------
__global__ void k_quantize(const float* __restrict__ w, int n4) {
    const float s = g_scales[1];
    const float4* p = (const float4*)w;
    float4* q = (float4*)g_qw;
    for (int i = blockIdx.x * blockDim.x + threadIdx.x; i < n4;
         i += gridDim.x * blockDim.x) {
        float4 v = p[i];
        float4 r;
        r.x = (fabsf(v.x / s) > 0.5f) ? (v.x > 0.f ? 1.f : -1.f) : 0.f;
        r.y = (fabsf(v.y / s) > 0.5f) ? (v.y > 0.f ? 1.f : -1.f) : 0.f;
        r.z = (fabsf(v.z / s) > 0.5f) ? (v.z > 0.f ? 1.f : -1.f) : 0.f;
        r.w = (fabsf(v.w / s) > 0.5f) ? (v.w > 0.f ? 1.f : -1.f) : 0.f;
        q[i] = r;
    }
}

// ---------------------------------------------------------------------------
// Pass 4: GEMM  out[m,n] = (sum_k x[m,k]*qw[n,k]) * ws + bias[n] * is
// CTA tile 128x128, BK=16, double-buffered smem, 8 warps (2x4), warp 64x32,
// tf32 mma.sync.m16n8k8 with fp32 accumulation.
// ---------------------------------------------------------------------------
#define BM 128
#define BN 128
#define BK 16
#define LDK 20  // +4 pad: conflict-free fragment LDS

__device__ __forceinline__ float f2tf32(float x) {
    uint32_t u;
    asm("cvt.rna.tf32.f32 %0, %1;" : "=r"(u) : "f"(x));
    return __uint_as_float(u);
}

__device__ __forceinline__ void mma_tf32(float c[4], const uint32_t a[4],
                                         const uint32_t b[2]) {
    asm volatile(
        "mma.sync.aligned.m16n8k8.row.col.f32.tf32.tf32.f32 "
        "{%0,%1,%2,%3}, {%4,%5,%6,%7}, {%8,%9}, {%0,%1,%2,%3};"
        : "+f"(c[0]), "+f"(c[1]), "+f"(c[2]), "+f"(c[3])
        : "r"(a[0]), "r"(a[1]), "r"(a[2]), "r"(a[3]), "r"(b[0]), "r"(b[1]));
}

__global__ void __launch_bounds__(256, 1)
k_gemm(const float* __restrict__ X, const float* __restrict__ bias,
       float* __restrict__ out) {
    __shared__ float sA[2][BM][LDK];
    __shared__ float sB[2][BN][LDK];

    const int tid  = threadIdx.x;
    const int m0   = blockIdx.y * BM;
    const int n0   = blockIdx.x * BN;
    const int warp = tid >> 5, lane = tid & 31;
    const int wm = (warp >> 2) * 64;   // 0 or 64
    const int wn = (warp & 3) * 32;    // 0,32,64,96
    const int grp = lane >> 2, tig = lane & 3;

    float acc[4][4][4];
#pragma unroll
    for (int i = 0; i < 4; i++)
#pragma unroll
        for (int j = 0; j < 4; j++)
#pragma unroll
            for (int r = 0; r < 4; r++) acc[i][j][r] = 0.f;

    // gmem tile pointers (float4 granularity). Row stride = K/4 = 1024 float4.
    const float4* gA = (const float4*)(X + (size_t)m0 * K_TOT);
    const float4* gB = (const float4*)(g_qw + (size_t)n0 * K_TOT);

    // per-thread load map: idx = tid + i*256; row = idx>>2; c4 = idx&3
    const int r0 = tid >> 2, c0 = tid & 3;          // i = 0 -> rows 0..63
    const int r1 = (tid + 256) >> 2;                 // i = 1 -> rows 64..127

    float4 ra[2], rb[2];

    auto loadRegs = [&](int kt) {
        ra[0] = gA[(size_t)r0 * 1024 + kt * 4 + c0];
        ra[1] = gA[(size_t)r1 * 1024 + kt * 4 + c0];
        rb[0] = gB[(size_t)r0 * 1024 + kt * 4 + c0];
        rb[1] = gB[(size_t)r1 * 1024 + kt * 4 + c0];
    };
    auto storeSmem = [&](int b) {
        float4 a0 = ra[0], a1 = ra[1];
        a0.x = f2tf32(a0.x); a0.y = f2tf32(a0.y); a0.z = f2tf32(a0.z); a0.w = f2tf32(a0.w);
        a1.x = f2tf32(a1.x); a1.y = f2tf32(a1.y); a1.z = f2tf32(a1.z); a1.w = f2tf32(a1.w);
        *(float4*)&sA[b][r0][c0 * 4] = a0;
        *(float4*)&sA[b][r1][c0 * 4] = a1;
        *(float4*)&sB[b][r0][c0 * 4] = rb[0];  // ternary values exact in tf32
        *(float4*)&sB[b][r1][c0 * 4] = rb[1];
    };

    loadRegs(0);
    storeSmem(0);
    __syncthreads();

    int buf = 0;
    const int KT = K_TOT / BK;  // 256
    for (int kt = 0; kt < KT; kt++) {
        if (kt + 1 < KT) loadRegs(kt + 1);

#pragma unroll
        for (int ks = 0; ks < BK; ks += 8) {
            uint32_t a[4][4], b[4][2];
#pragma unroll
            for (int mi = 0; mi < 4; mi++) {
                const int r = wm + mi * 16 + grp;
                a[mi][0] = __float_as_uint(sA[buf][r][ks + tig]);
                a[mi][1] = __float_as_uint(sA[buf][r + 8][ks + tig]);
                a[mi][2] = __float_as_uint(sA[buf][r][ks + tig + 4]);
                a[mi][3] = __float_as_uint(sA[buf][r + 8][ks + tig + 4]);
            }
#pragma unroll
            for (int ni = 0; ni < 4; ni++) {
                const int rn = wn + ni * 8 + grp;
                b[ni][0] = __float_as_uint(sB[buf][rn][ks + tig]);
                b[ni][1] = __float_as_uint(sB[buf][rn][ks + tig + 4]);
            }
#pragma unroll
            for (int mi = 0; mi < 4; mi++)
#pragma unroll
                for (int ni = 0; ni < 4; ni++) mma_tf32(acc[mi][ni], a[mi], b[ni]);
        }

        if (kt + 1 < KT) {
            storeSmem(buf ^ 1);
            __syncthreads();
            buf ^= 1;
        }
    }

    // epilogue
    const float is = g_scales[0];
    const float ws = g_scales[1];
#pragma unroll
    for (int mi = 0; mi < 4; mi++) {
        const int m = m0 + wm + mi * 16 + grp;
#pragma unroll
        for (int ni = 0; ni < 4; ni++) {
            const int n = n0 + wn + ni * 8 + tig * 2;
            const float2 bv = *(const float2*)&bias[n];
            float2 o0, o1;
            o0.x = acc[mi][ni][0] * ws + bv.x * is;
            o0.y = acc[mi][ni][1] * ws + bv.y * is;
            o1.x = acc[mi][ni][2] * ws + bv.x * is;
            o1.y = acc[mi][ni][3] * ws + bv.y * is;
            *(float2*)&out[(size_t)m * N_TOT + n]       = o0;
            *(float2*)&out[(size_t)(m + 8) * N_TOT + n] = o1;
        }
    }
}

// ---------------------------------------------------------------------------
extern "C" void kernel_launch(void* const* d_in, const int* in_sizes, int n_in,
                              void* d_out, int out_size) {
    const float* x    = (const float*)d_in[0];  // [2,2048,4096]
    const float* w    = (const float*)d_in[1];  // [4096,4096]
    const float* bias = (const float*)d_in[2];  // [4096]
    float* out = (float*)d_out;

    const int n4 = NELEM / 4;  // 4194304 float4s

    k_reduce_abs<<<1024, 256>>>(x, n4, 0);
    k_reduce_abs<<<1024, 256>>>(w, n4, 1024);
    k_finalize<<<1, 256>>>();
    k_quantize<<<2048, 256>>>(w, n4);

    dim3 grid(N_TOT / BN, M_TOT / BM);  // (32, 32)
    k_gemm<<<grid, 256>>>(x, bias, out);
}

// round 3
// speedup vs baseline: 2.7309x; 2.7309x over previous
#include <cuda_runtime.h>
#include <cuda_fp16.h>
#include <cstdint>

// ---------------------------------------------------------------------------
// BitNetLinear (sm_103 portable path — tcgen05 is 'a'-gated and unavailable):
//   out = (x @ qw^T) * w_scale + bias * input_scale   (input_scale cancels in
//   the GEMM, so x is fed raw as fp16)
// GEMM M=N=K=4096 via mma.sync.m16n8k16 fp16->fp32, ldmatrix, 4-stage cp.async
// ---------------------------------------------------------------------------

#define NELEM 16777216   // 4096*4096
#define KTOT  4096
#define BM 128
#define BN 128
#define BK 32
#define STAGES 4
#define ROWB 80          // smem row: 32 halves = 64B + 16B pad (conflict-free)
#define STAGE_BYTES ((BM + BN) * ROWB)   // 20480
#define NKT (KTOT / BK)  // 128

// Scratch (__device__ globals: allocation-free rule)
__device__ __align__(128) __half g_xh[(size_t)NELEM];   // x as fp16
__device__ __align__(128) __half g_qwh[(size_t)NELEM];  // ternary weight, fp16
__device__ double g_part[2048];
__device__ float  g_scales[2];   // [0]=input_scale, [1]=w_scale

// ------------------------------ helpers -----------------------------------
__device__ __forceinline__ uint32_t smem_u32(const void* p) {
    uint32_t a;
    asm("{ .reg .u64 t; cvta.to.shared.u64 t, %1; cvt.u32.u64 %0, t; }"
        : "=r"(a) : "l"(p));
    return a;
}
__device__ __forceinline__ void cp16(uint32_t s, const void* g) {
    asm volatile("cp.async.cg.shared.global [%0], [%1], 16;" :: "r"(s), "l"(g));
}
__device__ __forceinline__ void ldmx4(uint32_t r[4], uint32_t addr) {
    asm volatile("ldmatrix.sync.aligned.m8n8.x4.shared.b16 {%0,%1,%2,%3}, [%4];"
                 : "=r"(r[0]), "=r"(r[1]), "=r"(r[2]), "=r"(r[3]) : "r"(addr));
}
__device__ __forceinline__ void mma16816(float c[4], const uint32_t a[4],
                                         uint32_t b0, uint32_t b1) {
    asm volatile(
        "mma.sync.aligned.m16n8k16.row.col.f32.f16.f16.f32 "
        "{%0,%1,%2,%3}, {%4,%5,%6,%7}, {%8,%9}, {%0,%1,%2,%3};"
        : "+f"(c[0]), "+f"(c[1]), "+f"(c[2]), "+f"(c[3])
        : "r"(a[0]), "r"(a[1]), "r"(a[2]), "r"(a[3]), "r"(b0), "r"(b1));
}

// ---------------------------------------------------------------------------
// Pass 1a: reduce |x| (double) and convert x -> fp16 (fused)
// ---------------------------------------------------------------------------
__global__ void k_rx(const float* __restrict__ x, int n4) {
    double s = 0.0;
    const float4* p = (const float4*)x;
    __half2* q = (__half2*)g_xh;
    for (int i = blockIdx.x * blockDim.x + threadIdx.x; i < n4;
         i += gridDim.x * blockDim.x) {
        float4 v = p[i];
        s += (double)(fabsf(v.x) + fabsf(v.y)) + (double)(fabsf(v.z) + fabsf(v.w));
        q[2 * i]     = __floats2half2_rn(v.x, v.y);
        q[2 * i + 1] = __floats2half2_rn(v.z, v.w);
    }
    __shared__ double smd[256];
    smd[threadIdx.x] = s;
    __syncthreads();
    for (int o = 128; o > 0; o >>= 1) {
        if (threadIdx.x < o) smd[threadIdx.x] += smd[threadIdx.x + o];
        __syncthreads();
    }
    if (threadIdx.x == 0) g_part[blockIdx.x] = smd[0];
}

__global__ void k_rw(const float* __restrict__ w, int n4) {
    double s = 0.0;
    const float4* p = (const float4*)w;
    for (int i = blockIdx.x * blockDim.x + threadIdx.x; i < n4;
         i += gridDim.x * blockDim.x) {
        float4 v = p[i];
        s += (double)(fabsf(v.x) + fabsf(v.y)) + (double)(fabsf(v.z) + fabsf(v.w));
    }
    __shared__ double smd[256];
    smd[threadIdx.x] = s;
    __syncthreads();
    for (int o = 128; o > 0; o >>= 1) {
        if (threadIdx.x < o) smd[threadIdx.x] += smd[threadIdx.x + o];
        __syncthreads();
    }
    if (threadIdx.x == 0) g_part[1024 + blockIdx.x] = smd[0];
}

__global__ void k_finalize() {
    const int tid = threadIdx.x;
    __shared__ double smd[256];
    double sx = 0.0, sw = 0.0;
    for (int i = tid; i < 1024; i += 256) {
        sx += g_part[i];
        sw += g_part[1024 + i];
    }
    smd[tid] = sx;
    __syncthreads();
    for (int o = 128; o > 0; o >>= 1) {
        if (tid < o) smd[tid] += smd[tid + o];
        __syncthreads();
    }
    double totx = smd[0];
    __syncthreads();
    smd[tid] = sw;
    __syncthreads();
    for (int o = 128; o > 0; o >>= 1) {
        if (tid < o) smd[tid] += smd[tid + o];
        __syncthreads();
    }
    if (tid == 0) {
        g_scales[0] = fmaxf((float)(totx / (double)NELEM), 1e-8f);
        g_scales[1] = fmaxf((float)(smd[0] / (double)NELEM), 1e-8f);
    }
}

// Pass 3: ternary quantize weight -> fp16 {-1,0,1}   (matches |w/s| > 0.5)
__global__ void k_quant(const float* __restrict__ w, int n4) {
    const float s = g_scales[1];
    const __half one = __float2half(1.0f), mone = __float2half(-1.0f),
                 zero = __float2half(0.0f);
    const float4* p = (const float4*)w;
    __half2* q = (__half2*)g_qwh;
    for (int i = blockIdx.x * blockDim.x + threadIdx.x; i < n4;
         i += gridDim.x * blockDim.x) {
        float4 v = p[i];
        __half h0 = (fabsf(v.x / s) > 0.5f) ? (v.x > 0.f ? one : mone) : zero;
        __half h1 = (fabsf(v.y / s) > 0.5f) ? (v.y > 0.f ? one : mone) : zero;
        __half h2 = (fabsf(v.z / s) > 0.5f) ? (v.z > 0.f ? one : mone) : zero;
        __half h3 = (fabsf(v.w / s) > 0.5f) ? (v.w > 0.f ? one : mone) : zero;
        q[2 * i]     = __halves2half2(h0, h1);
        q[2 * i + 1] = __halves2half2(h2, h3);
    }
}

// ---------------------------------------------------------------------------
// Pass 4: GEMM.  CTA 128x128, BK=32, 4-stage cp.async, 8 warps (2x4),
// warp tile 64x32, mma.sync.m16n8k16 fp16->fp32 via ldmatrix.
// ---------------------------------------------------------------------------
__global__ void __launch_bounds__(256, 1)
k_gemm(const float* __restrict__ bias, float* __restrict__ out) {
    extern __shared__ char smem[];
    const uint32_t sb = smem_u32(smem);

    const int tid  = threadIdx.x;
    const int warp = tid >> 5, lane = tid & 31;
    const int m0 = blockIdx.y * BM, n0 = blockIdx.x * BN;
    const int wm = (warp >> 2) * 64;   // 0 or 64
    const int wn = (warp & 3) * 32;    // 0,32,64,96
    const int grp = lane >> 2, tig = lane & 3;

    float acc[4][4][4];
#pragma unroll
    for (int i = 0; i < 4; i++)
#pragma unroll
        for (int j = 0; j < 4; j++)
#pragma unroll
            for (int r = 0; r < 4; r++) acc[i][j][r] = 0.f;

    // gmem (16B vectors, row stride = 4096/8 = 512)
    const uint4* gA = (const uint4*)(g_xh  + (size_t)m0 * KTOT);
    const uint4* gB = (const uint4*)(g_qwh + (size_t)n0 * KTOT);

    // per-thread load map: chunk v in [0,512): row=v>>2, c=v&3
    const int lr0 = tid >> 2, lc0 = tid & 3;
    const int lr1 = (tid + 256) >> 2;

    auto issue = [&](int kt, int buf) {
        const uint32_t bA = sb + buf * STAGE_BYTES;
        const uint32_t bB = bA + BM * ROWB;
        cp16(bA + lr0 * ROWB + lc0 * 16, gA + (size_t)lr0 * 512 + kt * 4 + lc0);
        cp16(bA + lr1 * ROWB + lc0 * 16, gA + (size_t)lr1 * 512 + kt * 4 + lc0);
        cp16(bB + lr0 * ROWB + lc0 * 16, gB + (size_t)lr0 * 512 + kt * 4 + lc0);
        cp16(bB + lr1 * ROWB + lc0 * 16, gB + (size_t)lr1 * 512 + kt * 4 + lc0);
    };

    // ldmatrix lane addressing: rows (lane&15), k-chunk select (lane>>4)
    const int lrow = lane & 15, lsel = lane >> 4;

    auto compute = [&](int buf) {
        const uint32_t bA = sb + buf * STAGE_BYTES;
        const uint32_t bB = bA + BM * ROWB;
#pragma unroll
        for (int ks = 0; ks < 2; ks++) {
            const uint32_t kcol = (uint32_t)(ks * 2 + lsel) * 16;
            uint32_t a[4][4], b[2][4];
#pragma unroll
            for (int mi = 0; mi < 4; mi++)
                ldmx4(a[mi], bA + (uint32_t)(wm + mi * 16 + lrow) * ROWB + kcol);
#pragma unroll
            for (int bi = 0; bi < 2; bi++)
                ldmx4(b[bi], bB + (uint32_t)(wn + bi * 16 + lrow) * ROWB + kcol);
#pragma unroll
            for (int mi = 0; mi < 4; mi++) {
                mma16816(acc[mi][0], a[mi], b[0][0], b[0][2]);
                mma16816(acc[mi][1], a[mi], b[0][1], b[0][3]);
                mma16816(acc[mi][2], a[mi], b[1][0], b[1][2]);
                mma16816(acc[mi][3], a[mi], b[1][1], b[1][3]);
            }
        }
    };

    // prologue: fill STAGES-1 stages
#pragma unroll
    for (int s = 0; s < STAGES - 1; s++) {
        issue(s, s);
        asm volatile("cp.async.commit_group;" ::: "memory");
    }

    for (int kt = 0; kt < NKT; kt++) {
        asm volatile("cp.async.wait_group %0;" :: "n"(STAGES - 2) : "memory");
        __syncthreads();
        compute(kt & (STAGES - 1));
        if (kt + STAGES - 1 < NKT)
            issue(kt + STAGES - 1, (kt + STAGES - 1) & (STAGES - 1));
        asm volatile("cp.async.commit_group;" ::: "memory");
    }

    // epilogue
    const float ws = g_scales[1], is = g_scales[0];
#pragma unroll
    for (int mi = 0; mi < 4; mi++) {
        const int m = m0 + wm + mi * 16 + grp;
#pragma unroll
        for (int ni = 0; ni < 4; ni++) {
            const int n = n0 + wn + ni * 8 + tig * 2;
            const float2 bv = *(const float2*)&bias[n];
            float2 o0, o1;
            o0.x = acc[mi][ni][0] * ws + bv.x * is;
            o0.y = acc[mi][ni][1] * ws + bv.y * is;
            o1.x = acc[mi][ni][2] * ws + bv.x * is;
            o1.y = acc[mi][ni][3] * ws + bv.y * is;
            *(float2*)&out[(size_t)m * 4096 + n]       = o0;
            *(float2*)&out[(size_t)(m + 8) * 4096 + n] = o1;
        }
    }
}

// ---------------------------------------------------------------------------
extern "C" void kernel_launch(void* const* d_in, const int* in_sizes, int n_in,
                              void* d_out, int out_size) {
    const float* x    = (const float*)d_in[0];
    const float* w    = (const float*)d_in[1];
    const float* bias = (const float*)d_in[2];
    float* out = (float*)d_out;

    const int n4 = NELEM / 4;
    const int SMEM_BYTES = STAGES * STAGE_BYTES;  // 81920

    cudaFuncSetAttribute(k_gemm, cudaFuncAttributeMaxDynamicSharedMemorySize,
                         SMEM_BYTES);

    k_rx<<<1024, 256>>>(x, n4);
    k_rw<<<1024, 256>>>(w, n4);
    k_finalize<<<1, 256>>>();
    k_quant<<<2048, 256>>>(w, n4);

    dim3 grid(4096 / BN, 4096 / BM);  // (32, 32)
    k_gemm<<<grid, 256, SMEM_BYTES>>>(bias, out);
}